// round 1
// baseline (speedup 1.0000x reference)
#include <cuda_runtime.h>
#include <math.h>

#define BATCH 4096
#define DX 128
#define TT 81
#define DH 1024
#define KIN 257
#define KINP 264
#define DD 128
#define NSTEP 64
#define NDLY 16
#define DTC 0.02f
#define EPSB 1e-5f

// ---------------- device scratch (no cudaMalloc allowed) ----------------
__device__ float g_inpt[BATCH * KINP];   // gathered MLP input [4096][264]
__device__ float g_s0[BATCH * DH];       // activation ping
__device__ float g_s1[BATCH * DH];       // activation pong
__device__ float g_zt[BATCH * DD];       // z_t output of the MLP
__device__ float g_a[DH];                // per-feature BN scale (folded)
__device__ float g_c[DH];                // per-feature BN shift (folded)
__device__ float g_csum[DH];             // column sum accumulator
__device__ float g_csq[DH];              // column sumsq accumulator
__device__ float g_xsum[DX * TT];        // precomputed x column sums (all t)
__device__ float g_xsq[DX * TT];

// ---------------- init: y/z history prefix + y_t, zero xstats ----------------
__global__ void init_kernel(float* yt, float* __restrict__ y, float* __restrict__ z,
                            const float* __restrict__ y0) {
    int b = blockIdx.x;
    float v = y0[0];
    for (int q = threadIdx.x; q < DD * (NDLY + 1); q += blockDim.x) {
        int d = q / (NDLY + 1), t = q % (NDLY + 1);
        z[(size_t)b * DD * TT + d * TT + t] = 0.f;
    }
    if (threadIdx.x < NDLY + 1) y[b * TT + threadIdx.x] = v;
    if (threadIdx.x == 0) yt[b] = v;
}

__global__ void zero_xstats_kernel() {
    int i = blockIdx.x * blockDim.x + threadIdx.x;
    if (i < DX * TT) { g_xsum[i] = 0.f; g_xsq[i] = 0.f; }
}

// x is fixed across steps: column stats for every (feature d, time t) slice, once.
__global__ void xstats_kernel(const float* __restrict__ x) {
    int d = blockIdx.x, bc = blockIdx.y, j = threadIdx.x;
    if (j >= TT) return;
    float s = 0.f, q = 0.f;
    const float* base = x + (size_t)bc * 512 * DX * TT + (size_t)d * TT + j;
    for (int b = 0; b < 512; b++) {
        float v = base[(size_t)b * DX * TT];
        s += v; q += v * v;
    }
    atomicAdd(&g_xsum[d * TT + j], s);
    atomicAdd(&g_xsq[d * TT + j], q);
}

// ---------------- per-step: input BN coefficients from precomputed stats ----------------
__global__ void bn_in_prep_kernel(const float* __restrict__ gg, const float* __restrict__ bb, int i) {
    int k = threadIdx.x;          // blockDim = 1024
    int it = i + NDLY;
    if (k < KINP) {
        float a = 0.f, c = 0.f;
        if (k < 2 * DX) {
            int d  = (k < DX) ? k  : k - DX;
            int tt = (k < DX) ? it : i;
            float s = g_xsum[d * TT + tt], q = g_xsq[d * TT + tt];
            float m = s * (1.f / BATCH);
            float v = q * (1.f / BATCH) - m * m;
            if (v < 0.f) v = 0.f;
            a = gg[k] * rsqrtf(v + EPSB);
            c = bb[k] - m * a;
        } else if (k == 2 * DX) {
            // constant-t column: var==0 exactly -> normalized value == beta
            a = 0.f; c = bb[k];
        }
        g_a[k] = a; g_c[k] = c;
    }
    g_csum[k] = 0.f; g_csq[k] = 0.f;   // zero stat accumulators for first GEMM
}

// materialize the [x_t, x_delay, t] concat, padded to 264 cols
__global__ void gather_kernel(const float* __restrict__ x, int i) {
    int idx = blockIdx.x * blockDim.x + threadIdx.x;
    int b = idx / KINP, k = idx % KINP;
    int it = i + NDLY;
    float v;
    if (k < DX)            v = x[(size_t)b * DX * TT + k * TT + it];
    else if (k < 2 * DX)   v = x[(size_t)b * DX * TT + (k - DX) * TT + i];
    else if (k == 2 * DX)  v = (float)i * DTC;
    else                   v = 0.f;
    g_inpt[idx] = v;
}

// ---------------- fused BN(A) @ W + bias [+tanh] [+column stats] ----------------
// BM=BN=128, BK=8, 8x8 per thread, 256 threads.
__global__ __launch_bounds__(256, 2)
void gemm_bn_kernel(const float* __restrict__ A, int lda, int ktiles, int kreal,
                    const float* __restrict__ W, int N,
                    const float* __restrict__ bias,
                    float* __restrict__ out,
                    int do_tanh, int do_stats) {
    __shared__ float As[8][128];
    __shared__ float Ws[8][132];
    __shared__ float scol[128];
    __shared__ float ssq[128];

    int tid = threadIdx.x;
    int mBase = blockIdx.y * 128;
    int nBase = blockIdx.x * 128;

    int ar = tid >> 1;            // 0..127
    int ak = (tid & 1) * 4;       // 0 or 4
    int wk = tid >> 5;            // 0..7
    int wn = (tid & 31) * 4;      // 0..124

    int tm = (tid >> 4) * 8;
    int tn = (tid & 15) * 8;

    float acc[8][8];
#pragma unroll
    for (int i = 0; i < 8; i++)
#pragma unroll
        for (int j = 0; j < 8; j++) acc[i][j] = 0.f;

    const float* Aptr = A + (size_t)(mBase + ar) * lda;

    for (int kt = 0; kt < ktiles; ++kt) {
        int k0 = kt * 8;
        float4 av = *(const float4*)(Aptr + k0 + ak);
        float4 a4 = *(const float4*)(g_a + k0 + ak);
        float4 c4 = *(const float4*)(g_c + k0 + ak);
        As[ak + 0][ar] = fmaf(av.x, a4.x, c4.x);
        As[ak + 1][ar] = fmaf(av.y, a4.y, c4.y);
        As[ak + 2][ar] = fmaf(av.z, a4.z, c4.z);
        As[ak + 3][ar] = fmaf(av.w, a4.w, c4.w);

        int krow = k0 + wk;
        float4 wv;
        if (krow < kreal) wv = *(const float4*)(W + (size_t)krow * N + nBase + wn);
        else              wv = make_float4(0.f, 0.f, 0.f, 0.f);
        *(float4*)&Ws[wk][wn] = wv;
        __syncthreads();

#pragma unroll
        for (int kk = 0; kk < 8; ++kk) {
            float4 m0 = *(const float4*)&As[kk][tm];
            float4 m1 = *(const float4*)&As[kk][tm + 4];
            float4 n0 = *(const float4*)&Ws[kk][tn];
            float4 n1 = *(const float4*)&Ws[kk][tn + 4];
            float rm[8] = {m0.x, m0.y, m0.z, m0.w, m1.x, m1.y, m1.z, m1.w};
            float rn[8] = {n0.x, n0.y, n0.z, n0.w, n1.x, n1.y, n1.z, n1.w};
#pragma unroll
            for (int i = 0; i < 8; i++)
#pragma unroll
                for (int j = 0; j < 8; j++)
                    acc[i][j] = fmaf(rm[i], rn[j], acc[i][j]);
        }
        __syncthreads();
    }

    float bj[8];
#pragma unroll
    for (int j = 0; j < 8; j++) bj[j] = bias[nBase + tn + j];

    float cs[8], cq[8];
#pragma unroll
    for (int j = 0; j < 8; j++) { cs[j] = 0.f; cq[j] = 0.f; }

#pragma unroll
    for (int i = 0; i < 8; i++) {
        float v[8];
#pragma unroll
        for (int j = 0; j < 8; j++) {
            float t = acc[i][j] + bj[j];
            if (do_tanh) t = tanhf(t);
            v[j] = t;
            cs[j] += t;
            cq[j] += t * t;
        }
        float4* o = (float4*)(out + (size_t)(mBase + tm + i) * N + nBase + tn);
        o[0] = make_float4(v[0], v[1], v[2], v[3]);
        o[1] = make_float4(v[4], v[5], v[6], v[7]);
    }

    if (do_stats) {
        if (tid < 128) { scol[tid] = 0.f; ssq[tid] = 0.f; }
        __syncthreads();
#pragma unroll
        for (int j = 0; j < 8; j++) {
            atomicAdd(&scol[tn + j], cs[j]);
            atomicAdd(&ssq[tn + j], cq[j]);
        }
        __syncthreads();
        if (tid < 128) {
            atomicAdd(&g_csum[nBase + tid], scol[tid]);
            atomicAdd(&g_csq[nBase + tid], ssq[tid]);
        }
    }
}

// turn accumulated column stats into folded BN coefficients, re-zero accumulators
__global__ void finalize_bn_kernel(const float* __restrict__ gg, const float* __restrict__ bb) {
    int n = blockIdx.x * blockDim.x + threadIdx.x;
    if (n < DH) {
        float m = g_csum[n] * (1.f / BATCH);
        float v = g_csq[n] * (1.f / BATCH) - m * m;
        if (v < 0.f) v = 0.f;
        float a = gg[n] * rsqrtf(v + EPSB);
        g_a[n] = a;
        g_c[n] = bb[n] - m * a;
        g_csum[n] = 0.f;
        g_csq[n] = 0.f;
    }
}

// ---------------- per-step state update: driver f, vol, y/z writes ----------------
__global__ void update_kernel(const float* __restrict__ x, const float* __restrict__ dW,
                              float* yt, float* __restrict__ y, float* __restrict__ z, int i) {
    int b = blockIdx.x, d = threadIdx.x;   // 128 threads
    int it = i + NDLY;
    float zt = g_zt[b * DD + d];
    float zd = z[(size_t)b * DD * TT + d * TT + i];
    float xv = x[(size_t)b * DX * TT + d * TT + it];
    float dw = dW[(size_t)b * DD * NSTEP + d * NSTEP + i];
    z[(size_t)b * DD * TT + d * TT + it + 1] = zt;

    float p1 = zt * zd;   // sum(z_t * z_delay)
    float p2 = zt * dw;   // vol = z_t @ dW
    float p3 = xv;        // sum(x_t)
#pragma unroll
    for (int off = 16; off; off >>= 1) {
        p1 += __shfl_down_sync(0xffffffffu, p1, off);
        p2 += __shfl_down_sync(0xffffffffu, p2, off);
        p3 += __shfl_down_sync(0xffffffffu, p3, off);
    }
    __shared__ float red[3][4];
    int w = d >> 5, lane = d & 31;
    if (lane == 0) { red[0][w] = p1; red[1][w] = p2; red[2][w] = p3; }
    __syncthreads();
    if (d == 0) {
        float s1 = red[0][0] + red[0][1] + red[0][2] + red[0][3];
        float s2 = red[1][0] + red[1][1] + red[1][2] + red[1][3];
        float s3 = red[2][0] + red[2][1] + red[2][2] + red[2][3];
        float ytp = yt[b];
        float yd  = y[b * TT + i];
        float drv = -ytp + 0.1f * yd + s1 + 0.01f * s3;
        float yn  = ytp - drv * DTC + s2;
        yt[b] = yn;
        y[b * TT + it + 1] = yn;
    }
}

// ---------------- host launch ----------------
static float* sym_addr(const void* sym) {
    void* p = nullptr;
    cudaGetSymbolAddress(&p, sym);
    return (float*)p;
}

extern "C" void kernel_launch(void* const* d_in, const int* in_sizes, int n_in,
                              void* d_out, int out_size) {
    const float* x        = (const float*)d_in[0];
    const float* dW       = (const float*)d_in[1];
    const float* y0       = (const float*)d_in[2];
    const float* bn_in_g  = (const float*)d_in[3];
    const float* bn_in_b  = (const float*)d_in[4];
    const float* W_in     = (const float*)d_in[5];
    const float* b_in     = (const float*)d_in[6];
    const float* Ws_h     = (const float*)d_in[7];
    const float* bs_h     = (const float*)d_in[8];
    const float* bns_g    = (const float*)d_in[9];
    const float* bns_b    = (const float*)d_in[10];
    const float* bn_out_g = (const float*)d_in[11];
    const float* bn_out_b = (const float*)d_in[12];
    const float* W_out    = (const float*)d_in[13];
    const float* b_out    = (const float*)d_in[14];

    float* yt = (float*)d_out;                 // [B]
    float* y  = yt + BATCH;                    // [B][T]
    float* z  = y + (size_t)BATCH * TT;        // [B][DD][T]

    float* inpt = sym_addr(g_inpt);
    float* s0   = sym_addr(g_s0);
    float* s1   = sym_addr(g_s1);
    float* zt   = sym_addr(g_zt);

    init_kernel<<<BATCH, 256>>>(yt, y, z, y0);
    zero_xstats_kernel<<<(DX * TT + 255) / 256, 256>>>();
    xstats_kernel<<<dim3(DX, 8), 128>>>(x);

    dim3 gemmGridH(8, 32);   // N=1024
    dim3 gemmGridO(1, 32);   // N=128

    for (int i = 0; i < NSTEP; ++i) {
        bn_in_prep_kernel<<<1, 1024>>>(bn_in_g, bn_in_b, i);
        gather_kernel<<<(BATCH * KINP) / 256, 256>>>(x, i);

        // input layer: [4096,264(257)] @ [257,1024], tanh, collect stats
        gemm_bn_kernel<<<gemmGridH, 256>>>(inpt, KINP, KINP / 8, KIN,
                                           W_in, DH, b_in, s0, 1, 1);
        finalize_bn_kernel<<<4, 256>>>(bns_g + 0 * DH, bns_b + 0 * DH);

        gemm_bn_kernel<<<gemmGridH, 256>>>(s0, DH, DH / 8, DH,
                                           Ws_h + 0 * DH * DH, DH, bs_h + 0 * DH, s1, 1, 1);
        finalize_bn_kernel<<<4, 256>>>(bns_g + 1 * DH, bns_b + 1 * DH);

        gemm_bn_kernel<<<gemmGridH, 256>>>(s1, DH, DH / 8, DH,
                                           Ws_h + 1 * (size_t)DH * DH, DH, bs_h + 1 * DH, s0, 1, 1);
        finalize_bn_kernel<<<4, 256>>>(bns_g + 2 * DH, bns_b + 2 * DH);

        gemm_bn_kernel<<<gemmGridH, 256>>>(s0, DH, DH / 8, DH,
                                           Ws_h + 2 * (size_t)DH * DH, DH, bs_h + 2 * DH, s1, 1, 1);
        finalize_bn_kernel<<<4, 256>>>(bn_out_g, bn_out_b);

        // output layer: [4096,1024] @ [1024,128], no tanh, no stats
        gemm_bn_kernel<<<gemmGridO, 256>>>(s1, DH, DH / 8, DH,
                                           W_out, DD, b_out, zt, 0, 0);

        update_kernel<<<BATCH, DD>>>(x, dW, yt, y, z, i);
    }
}

// round 4
// speedup vs baseline: 1.5811x; 1.5811x over previous
#include <cuda_runtime.h>
#include <math.h>
#include <stdint.h>

#define BATCH 4096
#define DX 128
#define TT 81
#define DH 1024
#define KIN 257
#define KINP 288
#define DD 128
#define NSTEP 64
#define NDLY 16
#define DTC 0.02f
#define EPSB 1e-5f

#define KT_IN 36      /* 288/8  k-tiles, input layer  */
#define KT_H  128     /* 1024/8 k-tiles, hidden/out   */

/* B' (weights, split+tiled) region offsets in floats */
#define BIN_OFF  0
#define BIN_SZ   (128 * KT_IN * 128)
#define BH_OFF   (BIN_OFF + BIN_SZ)
#define BH_SZ    (128 * KT_H * 128)
#define BOUT_OFF (BH_OFF + 3 * BH_SZ)
#define BOUT_SZ  (16 * KT_H * 128)
#define BSP_TOTAL (BOUT_OFF + BOUT_SZ)

// ---------------- device scratch ----------------
__device__ float g_Bsp[BSP_TOTAL];            // weights split hi/lo, tile layout
__device__ float g_Asp[256 * KT_H * 32 * 8];  // activations split, tile layout
__device__ float g_s0[BATCH * DH];
__device__ float g_s1[BATCH * DH];
__device__ float g_zt[BATCH * DD];
__device__ float g_cs[4][DH];                 // per-layer column-sum accumulators
__device__ float g_cq[4][DH];                 // per-layer column-sumsq accumulators
__device__ float g_xsum[DX * TT];
__device__ float g_xsq[DX * TT];

// ---------------- helpers ----------------
__device__ __forceinline__ uint32_t smem_u32(const void* p) {
    uint32_t a;
    asm("{ .reg .u64 t; cvta.to.shared.u64 t, %1; cvt.u32.u64 %0, t; }" : "=r"(a) : "l"(p));
    return a;
}
__device__ __forceinline__ uint32_t tf32_rna(float x) {
    uint32_t u; asm("cvt.rna.tf32.f32 %0, %1;" : "=r"(u) : "f"(x)); return u;
}
__device__ __forceinline__ void split_tf32(float x, float& h, float& l) {
    uint32_t hu = tf32_rna(x);
    float hf = __uint_as_float(hu);
    h = hf;
    l = __uint_as_float(tf32_rna(x - hf));
}
__device__ __forceinline__ void lds128(uint32_t* r, uint32_t a) {
    asm volatile("ld.shared.v4.b32 {%0,%1,%2,%3}, [%4];"
                 : "=r"(r[0]), "=r"(r[1]), "=r"(r[2]), "=r"(r[3]) : "r"(a));
}
__device__ __forceinline__ void cpasync16(uint32_t s, const void* g) {
    asm volatile("cp.async.cg.shared.global [%0], [%1], 16;" :: "r"(s), "l"(g));
}
#define CP_COMMIT() asm volatile("cp.async.commit_group;" ::: "memory")
#define CP_WAIT1()  asm volatile("cp.async.wait_group 1;" ::: "memory")
#define CP_WAIT0()  asm volatile("cp.async.wait_group 0;" ::: "memory")

__device__ __forceinline__ void mma8(float* d, const uint32_t* a, uint32_t b0, uint32_t b1) {
    asm volatile(
        "mma.sync.aligned.m16n8k8.row.col.f32.tf32.tf32.f32 "
        "{%0,%1,%2,%3}, {%4,%5,%6,%7}, {%8,%9}, {%0,%1,%2,%3};"
        : "+f"(d[0]), "+f"(d[1]), "+f"(d[2]), "+f"(d[3])
        : "r"(a[0]), "r"(a[1]), "r"(a[2]), "r"(a[3]), "r"(b0), "r"(b1));
}

// ---------------- setup kernels ----------------
__global__ void init_kernel(float* yt, float* __restrict__ y, float* __restrict__ z,
                            const float* __restrict__ y0) {
    int b = blockIdx.x;
    float v = y0[0];
    for (int q = threadIdx.x; q < DD * (NDLY + 1); q += blockDim.x) {
        int d = q / (NDLY + 1), t = q % (NDLY + 1);
        z[(size_t)b * DD * TT + d * TT + t] = 0.f;
    }
    if (threadIdx.x < NDLY + 1) y[b * TT + threadIdx.x] = v;
    if (threadIdx.x == 0) yt[b] = v;
}

__global__ void zero_scratch_kernel() {
    int i = blockIdx.x * blockDim.x + threadIdx.x;
    if (i < DX * TT) { g_xsum[i] = 0.f; g_xsq[i] = 0.f; }
    if (i < 4 * DH)  { ((float*)g_cs)[i] = 0.f; ((float*)g_cq)[i] = 0.f; }
}

__global__ void xstats_kernel(const float* __restrict__ x) {
    int d = blockIdx.x, bc = blockIdx.y, j = threadIdx.x;
    if (j >= TT) return;
    float s = 0.f, q = 0.f;
    const float* base = x + (size_t)bc * 512 * DX * TT + (size_t)d * TT + j;
    for (int b = 0; b < 512; b++) {
        float v = base[(size_t)b * DX * TT];
        s += v; q += v * v;
    }
    atomicAdd(&g_xsum[d * TT + j], s);
    atomicAdd(&g_xsq[d * TT + j], q);
}

// split all weights into tile-layout hi/lo planes (once per launch)
// B' layout: [ntile][ktile][lane(32)][b0h,b1h,b0l,b1l]
__global__ void split_w_kernel(const float* __restrict__ W_in, const float* __restrict__ Ws_h,
                               const float* __restrict__ W_out) {
    size_t i = (size_t)blockIdx.x * 256 + threadIdx.x;
    const size_t N_IN = (size_t)KINP * DH;
    const size_t N_H  = (size_t)DH * DH;
    const size_t N_O  = (size_t)DH * DD;
    if (i >= N_IN + 3 * N_H + N_O) return;
    int k, n, Kt; size_t base; float v;
    if (i < N_IN) {
        k = (int)(i / DH); n = (int)(i % DH);
        v = (k < KIN) ? W_in[(size_t)k * DH + n] : 0.f;
        Kt = KT_IN; base = BIN_OFF;
    } else if (i < N_IN + 3 * N_H) {
        size_t j = i - N_IN;
        int l = (int)(j / N_H); size_t r = j % N_H;
        k = (int)(r / DH); n = (int)(r % DH);
        v = Ws_h[(size_t)l * N_H + (size_t)k * DH + n];
        Kt = KT_H; base = BH_OFF + (size_t)l * BH_SZ;
    } else {
        size_t j = i - N_IN - 3 * N_H;
        k = (int)(j / DD); n = (int)(j % DD);
        v = W_out[(size_t)k * DD + n];
        Kt = KT_H; base = BOUT_OFF;
    }
    float h, l2;
    split_tf32(v, h, l2);
    int nt = n >> 3, kt = k >> 3;
    int lane = (n & 7) * 4 + (k & 3);
    int w = (k & 7) >> 2;
    size_t off = base + ((size_t)(nt * Kt + kt) * 32 + lane) * 4;
    g_Bsp[off + w]     = h;
    g_Bsp[off + w + 2] = l2;
}

// ---------------- per-step kernels ----------------
// gather + inline input-BN fold + split into A' tile layout (Kt=36)
__global__ void gather_split_kernel(const float* __restrict__ x,
                                    const float* __restrict__ gg,
                                    const float* __restrict__ bb, int i) {
    int idx = blockIdx.x * 256 + threadIdx.x;
    int lane = idx & 31;
    int t2 = idx >> 5;
    int kt = t2 % KT_IN, mt = t2 / KT_IN;
    int m0 = mt * 16 + (lane >> 2);
    int k0 = kt * 8 + (lane & 3);
    int it = i + NDLY;

    float av[2], cv[2];
#pragma unroll
    for (int h = 0; h < 2; h++) {
        int k = k0 + h * 4;
        float a = 0.f, c = 0.f;
        if (k < 2 * DX) {
            int d  = (k < DX) ? k  : k - DX;
            int tt = (k < DX) ? it : i;
            float s = g_xsum[d * TT + tt], q = g_xsq[d * TT + tt];
            float m = s * (1.f / BATCH);
            float v = q * (1.f / BATCH) - m * m;
            if (v < 0.f) v = 0.f;
            a = gg[k] * rsqrtf(v + EPSB);
            c = bb[k] - m * a;
        } else if (k == 2 * DX) {
            c = bb[k];      // constant-t column: var==0 analytically
        }
        av[h] = a; cv[h] = c;
    }

    float f[4];
#pragma unroll
    for (int r = 0; r < 4; r++) {
        int m = m0 + (r & 1) * 8;
        int k = k0 + (r & 2) * 2;
        int h = (r & 2) >> 1;
        float raw = 0.f;
        if (k < DX)            raw = x[(size_t)m * DX * TT + k * TT + it];
        else if (k < 2 * DX)   raw = x[(size_t)m * DX * TT + (k - DX) * TT + i];
        f[r] = fmaf(raw, av[h], cv[h]);
    }
    float4 hi, lo;
    split_tf32(f[0], hi.x, lo.x); split_tf32(f[1], hi.y, lo.y);
    split_tf32(f[2], hi.z, lo.z); split_tf32(f[3], hi.w, lo.w);
    float* dst = g_Asp + ((size_t)(mt * KT_IN + kt) * 32 + lane) * 8;
    ((float4*)dst)[0] = hi;
    ((float4*)dst)[1] = lo;
}

// inline BN finalize + fold + split into A' tile layout (Kt=128)
__global__ void foldsplit_kernel(const float* __restrict__ s,
                                 const float* __restrict__ gg,
                                 const float* __restrict__ bb,
                                 const float* __restrict__ csum,
                                 const float* __restrict__ csq) {
    int idx = blockIdx.x * 256 + threadIdx.x;
    int lane = idx & 31;
    int t2 = idx >> 5;
    int kt = t2 & 127, mt = t2 >> 7;
    int m0 = mt * 16 + (lane >> 2);
    int k0 = kt * 8 + (lane & 3);

    float av[2], cv[2];
#pragma unroll
    for (int h = 0; h < 2; h++) {
        int k = k0 + h * 4;
        float m = csum[k] * (1.f / BATCH);
        float v = csq[k] * (1.f / BATCH) - m * m;
        if (v < 0.f) v = 0.f;
        float a = gg[k] * rsqrtf(v + EPSB);
        av[h] = a;
        cv[h] = bb[k] - m * a;
    }

    const float* row0 = s + (size_t)m0 * DH;
    const float* row8 = row0 + (size_t)8 * DH;
    float f0 = fmaf(row0[k0],     av[0], cv[0]);
    float f1 = fmaf(row8[k0],     av[0], cv[0]);
    float f2 = fmaf(row0[k0 + 4], av[1], cv[1]);
    float f3 = fmaf(row8[k0 + 4], av[1], cv[1]);
    float4 hi, lo;
    split_tf32(f0, hi.x, lo.x); split_tf32(f1, hi.y, lo.y);
    split_tf32(f2, hi.z, lo.z); split_tf32(f3, hi.w, lo.w);
    float* dst = g_Asp + ((size_t)(mt * KT_H + kt) * 32 + lane) * 8;
    ((float4*)dst)[0] = hi;
    ((float4*)dst)[1] = lo;
}

// ---------------- 3xTF32 mma.sync GEMM (product-outermost ordering) ----------------
__device__ __forceinline__ void load_stage(uint32_t sbase, int st,
                                           const float* __restrict__ Ap,
                                           const float* __restrict__ Bp,
                                           int Kt, int mt0, int nt0, int kc, int tid) {
    uint32_t abase = sbase + st * 65536;
    uint32_t bbase = abase + 32768;
    const int akt = tid >> 6, acid = tid & 63;
    const int bnt = tid >> 7, brem = tid & 127;
    const int bkt = brem >> 5, bcid = brem & 31;
#pragma unroll
    for (int i = 0; i < 8; i++) {
        const float* src = Ap + ((size_t)(mt0 + i) * Kt + (kc * 4 + akt)) * 256 + acid * 4;
        cpasync16(abase + (uint32_t)(((i * 4 + akt) * 256 + acid * 4) * 4), src);
    }
#pragma unroll
    for (int i = 0; i < 8; i++) {
        int nt = i * 2 + bnt;
        const float* src = Bp + ((size_t)(nt0 + nt) * Kt + (kc * 4 + bkt)) * 128 + bcid * 4;
        cpasync16(bbase + (uint32_t)(((nt * 4 + bkt) * 128 + bcid * 4) * 4), src);
    }
}

__global__ __launch_bounds__(256, 1)
void gemm_mma_kernel(const float* __restrict__ Ap, const float* __restrict__ Bp,
                     int Kt, int chunks, const float* __restrict__ bias,
                     float* __restrict__ out, int ldo, int do_tanh,
                     float* __restrict__ csum, float* __restrict__ csq) {
    extern __shared__ float smf[];
    const uint32_t sbase = smem_u32(smf);
    const int tid = threadIdx.x;
    const int mt0 = blockIdx.y * 8;
    const int nt0 = blockIdx.x * 16;
    const int w = tid >> 5, lane = tid & 31;
    const int wm = w & 3, wn2 = w >> 2;

    float acc[2][8][4];
#pragma unroll
    for (int mi = 0; mi < 2; mi++)
#pragma unroll
        for (int ni = 0; ni < 8; ni++)
#pragma unroll
            for (int r = 0; r < 4; r++) acc[mi][ni][r] = 0.f;

    load_stage(sbase, 0, Ap, Bp, Kt, mt0, nt0, 0, tid);
    CP_COMMIT();

    for (int kc = 0; kc < chunks; kc++) {
        if (kc + 1 < chunks) {
            load_stage(sbase, (kc + 1) & 1, Ap, Bp, Kt, mt0, nt0, kc + 1, tid);
            CP_COMMIT();
            CP_WAIT1();
        } else {
            CP_WAIT0();
        }
        __syncthreads();
        const uint32_t abase = sbase + (kc & 1) * 65536;
        const uint32_t bbase = abase + 32768;
#pragma unroll
        for (int kk = 0; kk < 4; kk++) {
            uint32_t ah[2][4], al[2][4], bh[8][2], bl[8][2];
#pragma unroll
            for (int mi = 0; mi < 2; mi++) {
                int mt = wm * 2 + mi;
                uint32_t ad = abase + (uint32_t)((((mt * 4 + kk) * 32 + lane) * 8) * 4);
                lds128(ah[mi], ad);
                lds128(al[mi], ad + 16);
            }
#pragma unroll
            for (int ni = 0; ni < 8; ni++) {
                int nt = wn2 * 8 + ni;
                uint32_t bf[4];
                lds128(bf, bbase + (uint32_t)((((nt * 4 + kk) * 32 + lane) * 4) * 4));
                bh[ni][0] = bf[0]; bh[ni][1] = bf[1];
                bl[ni][0] = bf[2]; bl[ni][1] = bf[3];
            }
            // product-outermost: same-acc reuse distance = 16 mmas
#pragma unroll
            for (int ni = 0; ni < 8; ni++)
#pragma unroll
                for (int mi = 0; mi < 2; mi++)
                    mma8(acc[mi][ni], ah[mi], bh[ni][0], bh[ni][1]);   // hi*hi
#pragma unroll
            for (int ni = 0; ni < 8; ni++)
#pragma unroll
                for (int mi = 0; mi < 2; mi++)
                    mma8(acc[mi][ni], ah[mi], bl[ni][0], bl[ni][1]);   // hi*lo
#pragma unroll
            for (int ni = 0; ni < 8; ni++)
#pragma unroll
                for (int mi = 0; mi < 2; mi++)
                    mma8(acc[mi][ni], al[mi], bh[ni][0], bh[ni][1]);   // lo*hi
        }
        __syncthreads();
    }

    // epilogue (+ optional fused column stats)
    const int r = lane >> 2, q = lane & 3;
    float colacc[8][4];
#pragma unroll
    for (int ni = 0; ni < 8; ni++)
#pragma unroll
        for (int u = 0; u < 4; u++) colacc[ni][u] = 0.f;

#pragma unroll
    for (int mi = 0; mi < 2; mi++) {
        int m = mt0 * 16 + wm * 32 + mi * 16 + r;
#pragma unroll
        for (int ni = 0; ni < 8; ni++) {
            int n = nt0 * 8 + wn2 * 64 + ni * 8 + 2 * q;
            float b0 = __ldg(bias + n), b1 = __ldg(bias + n + 1);
            float v0 = acc[mi][ni][0] + b0;
            float v1 = acc[mi][ni][1] + b1;
            float v2 = acc[mi][ni][2] + b0;
            float v3 = acc[mi][ni][3] + b1;
            if (do_tanh) { v0 = tanhf(v0); v1 = tanhf(v1); v2 = tanhf(v2); v3 = tanhf(v3); }
            colacc[ni][0] += v0 + v2;
            colacc[ni][1] += v1 + v3;
            colacc[ni][2] += v0 * v0 + v2 * v2;
            colacc[ni][3] += v1 * v1 + v3 * v3;
            *(float2*)(out + (size_t)m * ldo + n) = make_float2(v0, v1);
            *(float2*)(out + (size_t)(m + 8) * ldo + n) = make_float2(v2, v3);
        }
    }

    if (csum != nullptr) {
        __shared__ float scol[128], ssq[128];
        if (tid < 128) { scol[tid] = 0.f; ssq[tid] = 0.f; }
        __syncthreads();
#pragma unroll
        for (int ni = 0; ni < 8; ni++) {
            float a0 = colacc[ni][0], a1 = colacc[ni][1];
            float q0 = colacc[ni][2], q1 = colacc[ni][3];
#pragma unroll
            for (int off = 4; off < 32; off <<= 1) {
                a0 += __shfl_xor_sync(0xffffffffu, a0, off);
                a1 += __shfl_xor_sync(0xffffffffu, a1, off);
                q0 += __shfl_xor_sync(0xffffffffu, q0, off);
                q1 += __shfl_xor_sync(0xffffffffu, q1, off);
            }
            if (r == 0) {
                int cn = wn2 * 64 + ni * 8 + 2 * q;
                atomicAdd(&scol[cn], a0);
                atomicAdd(&scol[cn + 1], a1);
                atomicAdd(&ssq[cn], q0);
                atomicAdd(&ssq[cn + 1], q1);
            }
        }
        __syncthreads();
        if (tid < 128) {
            int col = blockIdx.x * 128 + tid;
            atomicAdd(csum + col, scol[tid]);
            atomicAdd(csq + col, ssq[tid]);
        }
    }
}

// ---------------- per-step state update (+ zero next-step stat buffers) ----------------
__global__ void update_kernel(const float* __restrict__ x, const float* __restrict__ dW,
                              float* yt, float* __restrict__ y, float* __restrict__ z, int i) {
    int b = blockIdx.x, d = threadIdx.x;   // 128 threads
    if (b < 32) {
        int t = b * 128 + d;               // 0..4095
        ((float*)g_cs)[t] = 0.f;
        ((float*)g_cq)[t] = 0.f;
    }
    int it = i + NDLY;
    float zt = g_zt[b * DD + d];
    float zd = z[(size_t)b * DD * TT + d * TT + i];
    float xv = x[(size_t)b * DX * TT + d * TT + it];
    float dw = dW[(size_t)b * DD * NSTEP + d * NSTEP + i];
    z[(size_t)b * DD * TT + d * TT + it + 1] = zt;

    float p1 = zt * zd;
    float p2 = zt * dw;
    float p3 = xv;
#pragma unroll
    for (int off = 16; off; off >>= 1) {
        p1 += __shfl_down_sync(0xffffffffu, p1, off);
        p2 += __shfl_down_sync(0xffffffffu, p2, off);
        p3 += __shfl_down_sync(0xffffffffu, p3, off);
    }
    __shared__ float red[3][4];
    int w = d >> 5, lane = d & 31;
    if (lane == 0) { red[0][w] = p1; red[1][w] = p2; red[2][w] = p3; }
    __syncthreads();
    if (d == 0) {
        float s1 = red[0][0] + red[0][1] + red[0][2] + red[0][3];
        float s2 = red[1][0] + red[1][1] + red[1][2] + red[1][3];
        float s3 = red[2][0] + red[2][1] + red[2][2] + red[2][3];
        float ytp = yt[b];
        float yd  = y[b * TT + i];
        float drv = -ytp + 0.1f * yd + s1 + 0.01f * s3;
        float yn  = ytp - drv * DTC + s2;
        yt[b] = yn;
        y[b * TT + it + 1] = yn;
    }
}

// ---------------- host launch ----------------
static float* sym_addr(const void* sym) {
    void* p = nullptr;
    cudaGetSymbolAddress(&p, sym);
    return (float*)p;
}

#define GEMM_SMEM 131072

extern "C" void kernel_launch(void* const* d_in, const int* in_sizes, int n_in,
                              void* d_out, int out_size) {
    const float* x        = (const float*)d_in[0];
    const float* dW       = (const float*)d_in[1];
    const float* y0       = (const float*)d_in[2];
    const float* bn_in_g  = (const float*)d_in[3];
    const float* bn_in_b  = (const float*)d_in[4];
    const float* W_in     = (const float*)d_in[5];
    const float* b_in     = (const float*)d_in[6];
    const float* Ws_h     = (const float*)d_in[7];
    const float* bs_h     = (const float*)d_in[8];
    const float* bns_g    = (const float*)d_in[9];
    const float* bns_b    = (const float*)d_in[10];
    const float* bn_out_g = (const float*)d_in[11];
    const float* bn_out_b = (const float*)d_in[12];
    const float* W_out    = (const float*)d_in[13];
    const float* b_out    = (const float*)d_in[14];

    float* yt = (float*)d_out;
    float* y  = yt + BATCH;
    float* z  = y + (size_t)BATCH * TT;

    float* Asp = sym_addr(g_Asp);
    float* Bsp = sym_addr(g_Bsp);
    float* s0  = sym_addr(g_s0);
    float* s1  = sym_addr(g_s1);
    float* zt  = sym_addr(g_zt);
    float* cs  = sym_addr(g_cs);
    float* cq  = sym_addr(g_cq);

    cudaFuncSetAttribute(gemm_mma_kernel, cudaFuncAttributeMaxDynamicSharedMemorySize, GEMM_SMEM);

    init_kernel<<<BATCH, 256>>>(yt, y, z, y0);
    zero_scratch_kernel<<<(DX * TT + 255) / 256, 256>>>();
    xstats_kernel<<<dim3(DX, 8), 128>>>(x);
    split_w_kernel<<<13952, 256>>>(W_in, Ws_h, W_out);

    dim3 gridH(8, 32);   // N=1024
    dim3 gridO(1, 32);   // N=128

    for (int i = 0; i < NSTEP; ++i) {
        gather_split_kernel<<<(256 * KT_IN * 32) / 256, 256>>>(x, bn_in_g, bn_in_b, i);

        gemm_mma_kernel<<<gridH, 256, GEMM_SMEM>>>(Asp, Bsp + BIN_OFF, KT_IN, KT_IN / 4,
                                                   b_in, s0, DH, 1, cs + 0 * DH, cq + 0 * DH);
        foldsplit_kernel<<<(256 * KT_H * 32) / 256, 256>>>(s0, bns_g + 0 * DH, bns_b + 0 * DH,
                                                           cs + 0 * DH, cq + 0 * DH);

        gemm_mma_kernel<<<gridH, 256, GEMM_SMEM>>>(Asp, Bsp + BH_OFF, KT_H, KT_H / 4,
                                                   bs_h + 0 * DH, s1, DH, 1, cs + 1 * DH, cq + 1 * DH);
        foldsplit_kernel<<<(256 * KT_H * 32) / 256, 256>>>(s1, bns_g + 1 * DH, bns_b + 1 * DH,
                                                           cs + 1 * DH, cq + 1 * DH);

        gemm_mma_kernel<<<gridH, 256, GEMM_SMEM>>>(Asp, Bsp + BH_OFF + BH_SZ, KT_H, KT_H / 4,
                                                   bs_h + 1 * DH, s0, DH, 1, cs + 2 * DH, cq + 2 * DH);
        foldsplit_kernel<<<(256 * KT_H * 32) / 256, 256>>>(s0, bns_g + 2 * DH, bns_b + 2 * DH,
                                                           cs + 2 * DH, cq + 2 * DH);

        gemm_mma_kernel<<<gridH, 256, GEMM_SMEM>>>(Asp, Bsp + BH_OFF + 2 * BH_SZ, KT_H, KT_H / 4,
                                                   bs_h + 2 * DH, s1, DH, 1, cs + 3 * DH, cq + 3 * DH);
        foldsplit_kernel<<<(256 * KT_H * 32) / 256, 256>>>(s1, bn_out_g, bn_out_b,
                                                           cs + 3 * DH, cq + 3 * DH);

        gemm_mma_kernel<<<gridO, 256, GEMM_SMEM>>>(Asp, Bsp + BOUT_OFF, KT_H, KT_H / 4,
                                                   b_out, zt, DD, 0, nullptr, nullptr);

        update_kernel<<<BATCH, DD>>>(x, dW, yt, y, z, i);
    }
}